// round 11
// baseline (speedup 1.0000x reference)
#include <cuda_runtime.h>
#include <cstdint>

// Fixed problem shape: (N,C,H,W,T) = (8,16,32,32,500)
constexpr int N_ = 8;
constexpr int C_ = 16;
constexpr int H_ = 32;
constexpr int W_ = 32;
constexpr int T_ = 500;
constexpr int CHW = C_ * H_ * W_;     // 16384 (power of two)
constexpr int TV  = T_ / 4;           // 125 float4 per row
constexpr int NPER = 8;               // ALL batch rows per thread (hot path)
constexpr int ROWSTRIDE = CHW * TV;   // 2,048,000 float4 between n's (32-bit safe)

__global__ void __launch_bounds__(256, 5) delay_kernel(
    const float* __restrict__ x,
    const float* __restrict__ delay,
    const uint32_t* __restrict__ ts_bits,
    float* __restrict__ out)
{
    // 128 threads per chw; block covers 2 chw values; each thread does all 8 n.
    int tv   = threadIdx.x & 127;
    int chw  = (blockIdx.x << 1) | (threadIdx.x >> 7);
    int lane = threadIdx.x & 31;
    bool active = tv < TV;            // tail threads stay alive for shfl

    // Decode Ts robustly (scalar may arrive as int32 or float32 bits).
    uint32_t tb = __ldg(ts_bits);
    float tf = __uint_as_float(tb);
    float Ts = (tf >= 1e-6f && tf <= 1e6f) ? tf : (float)(int)tb;

    // Per-chw shift parameters — shared by all n.
    float s    = __ldg(delay + chw) / Ts;
    float sif  = floorf(s);
    float frac = s - sif;
    int   si   = (int)sif;

    int start = -1 - si;         // first tap offset
    int q0 = start >> 2;         // floor-div-4
    int r  = start & 3;          // warp-uniform extract case

    const float4* __restrict__ x4 = reinterpret_cast<const float4*>(x);
    float4* __restrict__ o4 = reinterpret_cast<float4*>(out);
    int obase = chw * TV + tv;

    float w1 = frac;
    float w0 = 1.0f - frac;
    float4 z = make_float4(0.f, 0.f, 0.f, 0.f);

    if (r == 3) {
        // HOT PATH (always taken for delay in [0,1), Ts=1):
        // taps = { V[wv-1].w, V[wv].x, V[wv].y, V[wv].z, V[wv].w }, wv = tv+q0+1.
        // One LDG.128 per (n, thread) — 8 independent loads front-batched
        // (in-flight index == R6) with zero duplicate line touches (== R7).
        int wv = tv + q0 + 1;
        bool vw = (wv >= 0) && (wv < TV);      // V[wv] validity (whole vector)
        bool vn = (wv >= 1) && (wv <= TV);     // element 4*wv-1 validity
        bool le = (lane == 0);

        int abase = chw * TV + wv;

        float4 Wv[NPER];
        float  Ew[NPER];
#pragma unroll
        for (int j = 0; j < NPER; ++j) {
            Wv[j] = vw ? __ldg(x4 + abase + j * ROWSTRIDE) : z;
            Ew[j] = (le && vn) ? __ldg(x + ((abase + j * ROWSTRIDE) << 2) - 1) : 0.0f;
        }

#pragma unroll
        for (int j = 0; j < NPER; ++j) {
            float nbw = __shfl_up_sync(0xffffffffu, Wv[j].w, 1);
            if (lane == 0) nbw = Ew[j];
            float4 o;
            o.x = w0 * Wv[j].x + w1 * nbw;
            o.y = w0 * Wv[j].y + w1 * Wv[j].x;
            o.z = w0 * Wv[j].z + w1 * Wv[j].y;
            o.w = w0 * Wv[j].w + w1 * Wv[j].z;
            if (active) o4[obase + j * ROWSTRIDE] = o;
        }
    } else {
        // FALLBACK (warp-uniform branch; never taken for this dataset).
        // Deliberately NOT unrolled so its register demand cannot inflate
        // the hot path's allocation (the R9 spill failure mode).
        if (!active) return;
        int vi = tv + q0;
        bool va = (vi     >= 0) && (vi     < TV);
        bool vb = (vi + 1 >= 0) && (vi + 1 < TV);
        int abase = chw * TV + vi;

#pragma unroll 1
        for (int j = 0; j < NPER; ++j) {
            float4 A = va ? __ldg(x4 + abase + j * ROWSTRIDE)     : z;
            float4 B = vb ? __ldg(x4 + abase + j * ROWSTRIDE + 1) : z;
            float l0, l1, l2, l3, l4;
            switch (r) {
                case 0: l0 = A.x; l1 = A.y; l2 = A.z; l3 = A.w; l4 = B.x; break;
                case 1: l0 = A.y; l1 = A.z; l2 = A.w; l3 = B.x; l4 = B.y; break;
                default:l0 = A.z; l1 = A.w; l2 = B.x; l3 = B.y; l4 = B.z; break;
            }
            float4 o;
            o.x = w0 * l1 + w1 * l0;
            o.y = w0 * l2 + w1 * l1;
            o.z = w0 * l3 + w1 * l2;
            o.w = w0 * l4 + w1 * l3;
            o4[obase + j * ROWSTRIDE] = o;
        }
    }
}

extern "C" void kernel_launch(void* const* d_in, const int* in_sizes, int n_in,
                              void* d_out, int out_size)
{
    const float*    x     = (const float*)d_in[0];
    const float*    delay = (const float*)d_in[1];
    const uint32_t* ts    = (const uint32_t*)d_in[2];
    float*          out   = (float*)d_out;

    // CHW/2 blocks of 256 threads; each block covers 2 chw, all 8 n.
    delay_kernel<<<CHW / 2, 256>>>(x, delay, ts, out);
}

// round 12
// speedup vs baseline: 1.0055x; 1.0055x over previous
#include <cuda_runtime.h>
#include <cstdint>

// Fixed problem shape: (N,C,H,W,T) = (8,16,32,32,500)
// R6 body (measured optimum: NPER=4, 8 front-batched LDG.128/thread, 40 regs,
// 6 blocks/SM) + evict-first stores: output is write-once/never-read, so keep
// it out of L2 and leave the cache to the doubly-touched input stream.
constexpr int N_ = 8;
constexpr int C_ = 16;
constexpr int H_ = 32;
constexpr int W_ = 32;
constexpr int T_ = 500;
constexpr int CHW = C_ * H_ * W_;     // 16384 (power of two)
constexpr int TV  = T_ / 4;           // 125 float4 per row
constexpr int NPER = 4;               // batch rows per thread
constexpr int ROWSTRIDE = CHW * TV;   // 2,048,000 float4 stride between n's (32-bit safe)

__device__ __forceinline__ void stcs4(float4* p, float4 v) {
    asm volatile("st.global.cs.v4.f32 [%0], {%1,%2,%3,%4};"
                 :: "l"(p), "f"(v.x), "f"(v.y), "f"(v.z), "f"(v.w)
                 : "memory");
}

__global__ void __launch_bounds__(256, 6) delay_kernel(
    const float* __restrict__ x,
    const float* __restrict__ delay,
    const uint32_t* __restrict__ ts_bits,
    float* __restrict__ out)
{
    // blockIdx encodes (chw pair, n-half). 128 threads per chw.
    int tv  = threadIdx.x & 127;
    int chw = ((blockIdx.x >> 1) << 1) | (threadIdx.x >> 7);
    int n0  = (blockIdx.x & 1) * NPER;
    if (tv >= TV) return;

    // Decode Ts robustly (scalar may arrive as int32 or float32 bits).
    uint32_t tb = __ldg(ts_bits);
    float tf = __uint_as_float(tb);
    float Ts = (tf >= 1e-6f && tf <= 1e6f) ? tf : (float)(int)tb;

    // Per-chw shift parameters — shared by all n.
    float s    = __ldg(delay + chw) / Ts;
    float sif  = floorf(s);
    float frac = s - sif;
    int   si   = (int)sif;

    int start = -1 - si;         // first tap offset
    int q0 = start >> 2;         // floor-div-4
    int r  = start & 3;          // warp-uniform extract case

    int vi = tv + q0;
    bool va = (vi     >= 0) && (vi     < TV);
    bool vb = (vi + 1 >= 0) && (vi + 1 < TV);

    // Pure 32-bit indexing: total float4 count = 16.384M << 2^31.
    const float4* __restrict__ x4 = reinterpret_cast<const float4*>(x);
    int abase = (n0 * CHW + chw) * TV + vi;

    // Front-batched independent loads: 8 x LDG.128 in flight (MLP_p1 = 8).
    float4 z = make_float4(0.f, 0.f, 0.f, 0.f);
    float4 A[NPER], B[NPER];
#pragma unroll
    for (int j = 0; j < NPER; ++j) {
        A[j] = va ? __ldg(x4 + (abase + j * ROWSTRIDE))     : z;
        B[j] = vb ? __ldg(x4 + (abase + j * ROWSTRIDE + 1)) : z;
    }

    float w1 = frac;
    float w0 = 1.0f - frac;
    float4* __restrict__ o4 = reinterpret_cast<float4*>(out);
    int obase = (n0 * CHW + chw) * TV + tv;

#pragma unroll
    for (int j = 0; j < NPER; ++j) {
        float l0, l1, l2, l3, l4;
        switch (r) {
            case 0: l0 = A[j].x; l1 = A[j].y; l2 = A[j].z; l3 = A[j].w; l4 = B[j].x; break;
            case 1: l0 = A[j].y; l1 = A[j].z; l2 = A[j].w; l3 = B[j].x; l4 = B[j].y; break;
            case 2: l0 = A[j].z; l1 = A[j].w; l2 = B[j].x; l3 = B[j].y; l4 = B[j].z; break;
            default:l0 = A[j].w; l1 = B[j].x; l2 = B[j].y; l3 = B[j].z; l4 = B[j].w; break;
        }
        float4 o;
        o.x = w0 * l1 + w1 * l0;
        o.y = w0 * l2 + w1 * l1;
        o.z = w0 * l3 + w1 * l2;
        o.w = w0 * l4 + w1 * l3;
        stcs4(o4 + obase + j * ROWSTRIDE, o);
    }
}

extern "C" void kernel_launch(void* const* d_in, const int* in_sizes, int n_in,
                              void* d_out, int out_size)
{
    const float*    x     = (const float*)d_in[0];
    const float*    delay = (const float*)d_in[1];
    const uint32_t* ts    = (const uint32_t*)d_in[2];
    float*          out   = (float*)d_out;

    // CHW blocks: each covers 2 chw values x one n-half (4 rows per thread).
    delay_kernel<<<CHW, 256>>>(x, delay, ts, out);
}

// round 13
// speedup vs baseline: 1.0251x; 1.0195x over previous
#include <cuda_runtime.h>
#include <cstdint>

// Fixed problem shape: (N,C,H,W,T) = (8,16,32,32,500)
//
// FINAL (R6 configuration — measured optimum over 12-round sweep):
//   - 128 threads per (c,h,w) row, 2 rows per 256-thread block, 4 batch
//     rows per thread (NPER=4) -> 8 front-batched independent LDG.128.
//   - Pure 32-bit indexing (40 regs), __launch_bounds__(256,6) -> 48 warps/SM.
//   - Per-row delay parameters computed once, amortized over 4 n-rows;
//     warp-uniform extract case r (floor(start/4) remainder).
// Measured: ~76 us kernel, DRAM ~78-79% of 8 TB/s spec, aggregate r+w
// ~6.5 TB/s == practical HBM3e mixed-stream ceiling. MLP>8, occ>64%,
// shfl dedup, and ld/st cache hints all measured neutral or regressive.
constexpr int N_ = 8;
constexpr int C_ = 16;
constexpr int H_ = 32;
constexpr int W_ = 32;
constexpr int T_ = 500;
constexpr int CHW = C_ * H_ * W_;     // 16384 (power of two)
constexpr int TV  = T_ / 4;           // 125 float4 per row
constexpr int NPER = 4;               // batch rows per thread
constexpr int ROWSTRIDE = CHW * TV;   // 2,048,000 float4 stride between n's (32-bit safe)

__global__ void __launch_bounds__(256, 6) delay_kernel(
    const float* __restrict__ x,
    const float* __restrict__ delay,
    const uint32_t* __restrict__ ts_bits,
    float* __restrict__ out)
{
    // blockIdx encodes (chw pair, n-half). 128 threads per chw.
    int tv  = threadIdx.x & 127;
    int chw = ((blockIdx.x >> 1) << 1) | (threadIdx.x >> 7);
    int n0  = (blockIdx.x & 1) * NPER;
    if (tv >= TV) return;

    // Decode Ts robustly (scalar may arrive as int32 or float32 bits).
    uint32_t tb = __ldg(ts_bits);
    float tf = __uint_as_float(tb);
    float Ts = (tf >= 1e-6f && tf <= 1e6f) ? tf : (float)(int)tb;

    // Per-chw shift parameters — shared by all n.
    float s    = __ldg(delay + chw) / Ts;
    float sif  = floorf(s);
    float frac = s - sif;
    int   si   = (int)sif;

    int start = -1 - si;         // first tap offset
    int q0 = start >> 2;         // floor-div-4
    int r  = start & 3;          // warp-uniform extract case

    int vi = tv + q0;
    bool va = (vi     >= 0) && (vi     < TV);
    bool vb = (vi + 1 >= 0) && (vi + 1 < TV);

    // Pure 32-bit indexing: total float4 count = 16.384M << 2^31.
    const float4* __restrict__ x4 = reinterpret_cast<const float4*>(x);
    int abase = (n0 * CHW + chw) * TV + vi;

    // Front-batched independent loads: 8 x LDG.128 in flight (MLP_p1 = 8).
    float4 z = make_float4(0.f, 0.f, 0.f, 0.f);
    float4 A[NPER], B[NPER];
#pragma unroll
    for (int j = 0; j < NPER; ++j) {
        A[j] = va ? __ldg(x4 + (abase + j * ROWSTRIDE))     : z;
        B[j] = vb ? __ldg(x4 + (abase + j * ROWSTRIDE + 1)) : z;
    }

    float w1 = frac;
    float w0 = 1.0f - frac;
    float4* __restrict__ o4 = reinterpret_cast<float4*>(out);
    int obase = (n0 * CHW + chw) * TV + tv;

#pragma unroll
    for (int j = 0; j < NPER; ++j) {
        float l0, l1, l2, l3, l4;
        switch (r) {
            case 0: l0 = A[j].x; l1 = A[j].y; l2 = A[j].z; l3 = A[j].w; l4 = B[j].x; break;
            case 1: l0 = A[j].y; l1 = A[j].z; l2 = A[j].w; l3 = B[j].x; l4 = B[j].y; break;
            case 2: l0 = A[j].z; l1 = A[j].w; l2 = B[j].x; l3 = B[j].y; l4 = B[j].z; break;
            default:l0 = A[j].w; l1 = B[j].x; l2 = B[j].y; l3 = B[j].z; l4 = B[j].w; break;
        }
        float4 o;
        o.x = w0 * l1 + w1 * l0;
        o.y = w0 * l2 + w1 * l1;
        o.z = w0 * l3 + w1 * l2;
        o.w = w0 * l4 + w1 * l3;
        o4[obase + j * ROWSTRIDE] = o;
    }
}

extern "C" void kernel_launch(void* const* d_in, const int* in_sizes, int n_in,
                              void* d_out, int out_size)
{
    const float*    x     = (const float*)d_in[0];
    const float*    delay = (const float*)d_in[1];
    const uint32_t* ts    = (const uint32_t*)d_in[2];
    float*          out   = (float*)d_out;

    // CHW blocks: each covers 2 chw values x one n-half (4 rows per thread).
    delay_kernel<<<CHW, 256>>>(x, delay, ts, out);
}

// round 14
// speedup vs baseline: 1.0255x; 1.0004x over previous
#include <cuda_runtime.h>
#include <cstdint>

// Fixed problem shape: (N,C,H,W,T) = (8,16,32,32,500)
//
// FINAL — measured optimum over a 13-round sweep on GB300 (sm_103a):
//   - 128 threads per (c,h,w) row, 2 rows per 256-thread block, 4 batch
//     rows per thread (NPER=4) -> 8 front-batched independent LDG.128.
//   - Pure 32-bit indexing (40 regs), __launch_bounds__(256,6) -> 48 warps/SM.
//   - Per-row delay parameters computed once, amortized over 4 n-rows;
//     warp-uniform extract case r = (-1-floor(delay/Ts)) mod 4.
// Measured: 74.6 us kernel / 80.35 us wall, DRAM 80.1% (6.35 TB/s), aggregate
// r+w ~6.5 TB/s == B300 LTS/HBM mixed-stream ceiling. All other axes
// (MLP 16, occ forcing, shfl dedup, ld.cs/st.cs) measured neutral or worse.
constexpr int N_ = 8;
constexpr int C_ = 16;
constexpr int H_ = 32;
constexpr int W_ = 32;
constexpr int T_ = 500;
constexpr int CHW = C_ * H_ * W_;     // 16384 (power of two)
constexpr int TV  = T_ / 4;           // 125 float4 per row
constexpr int NPER = 4;               // batch rows per thread
constexpr int ROWSTRIDE = CHW * TV;   // 2,048,000 float4 stride between n's (32-bit safe)

__global__ void __launch_bounds__(256, 6) delay_kernel(
    const float* __restrict__ x,
    const float* __restrict__ delay,
    const uint32_t* __restrict__ ts_bits,
    float* __restrict__ out)
{
    // blockIdx encodes (chw pair, n-half). 128 threads per chw.
    int tv  = threadIdx.x & 127;
    int chw = ((blockIdx.x >> 1) << 1) | (threadIdx.x >> 7);
    int n0  = (blockIdx.x & 1) * NPER;
    if (tv >= TV) return;

    // Decode Ts robustly (scalar may arrive as int32 or float32 bits).
    uint32_t tb = __ldg(ts_bits);
    float tf = __uint_as_float(tb);
    float Ts = (tf >= 1e-6f && tf <= 1e6f) ? tf : (float)(int)tb;

    // Per-chw shift parameters — shared by all n.
    float s    = __ldg(delay + chw) / Ts;
    float sif  = floorf(s);
    float frac = s - sif;
    int   si   = (int)sif;

    int start = -1 - si;         // first tap offset
    int q0 = start >> 2;         // floor-div-4
    int r  = start & 3;          // warp-uniform extract case

    int vi = tv + q0;
    bool va = (vi     >= 0) && (vi     < TV);
    bool vb = (vi + 1 >= 0) && (vi + 1 < TV);

    // Pure 32-bit indexing: total float4 count = 16.384M << 2^31.
    const float4* __restrict__ x4 = reinterpret_cast<const float4*>(x);
    int abase = (n0 * CHW + chw) * TV + vi;

    // Front-batched independent loads: 8 x LDG.128 in flight (MLP_p1 = 8).
    float4 z = make_float4(0.f, 0.f, 0.f, 0.f);
    float4 A[NPER], B[NPER];
#pragma unroll
    for (int j = 0; j < NPER; ++j) {
        A[j] = va ? __ldg(x4 + (abase + j * ROWSTRIDE))     : z;
        B[j] = vb ? __ldg(x4 + (abase + j * ROWSTRIDE + 1)) : z;
    }

    float w1 = frac;
    float w0 = 1.0f - frac;
    float4* __restrict__ o4 = reinterpret_cast<float4*>(out);
    int obase = (n0 * CHW + chw) * TV + tv;

#pragma unroll
    for (int j = 0; j < NPER; ++j) {
        float l0, l1, l2, l3, l4;
        switch (r) {
            case 0: l0 = A[j].x; l1 = A[j].y; l2 = A[j].z; l3 = A[j].w; l4 = B[j].x; break;
            case 1: l0 = A[j].y; l1 = A[j].z; l2 = A[j].w; l3 = B[j].x; l4 = B[j].y; break;
            case 2: l0 = A[j].z; l1 = A[j].w; l2 = B[j].x; l3 = B[j].y; l4 = B[j].z; break;
            default:l0 = A[j].w; l1 = B[j].x; l2 = B[j].y; l3 = B[j].z; l4 = B[j].w; break;
        }
        float4 o;
        o.x = w0 * l1 + w1 * l0;
        o.y = w0 * l2 + w1 * l1;
        o.z = w0 * l3 + w1 * l2;
        o.w = w0 * l4 + w1 * l3;
        o4[obase + j * ROWSTRIDE] = o;
    }
}

extern "C" void kernel_launch(void* const* d_in, const int* in_sizes, int n_in,
                              void* d_out, int out_size)
{
    const float*    x     = (const float*)d_in[0];
    const float*    delay = (const float*)d_in[1];
    const uint32_t* ts    = (const uint32_t*)d_in[2];
    float*          out   = (float*)d_out;

    // CHW blocks: each covers 2 chw values x one n-half (4 rows per thread).
    delay_kernel<<<CHW, 256>>>(x, delay, ts, out);
}

// round 15
// speedup vs baseline: 1.0300x; 1.0044x over previous
#include <cuda_runtime.h>
#include <cstdint>

// Fixed problem shape: (N,C,H,W,T) = (8,16,32,32,500)
//
// R13 optimum (NPER=4, 8 front-batched LDG.128/thread, 32-bit indexing,
// 40 regs @ 6 blocks/SM) with ONE change: the n-half selector moved from the
// LOW bit of blockIdx.x to the HIGH bit. Wave-concurrent blocks now stream
// one contiguous 131 MB input slab + one contiguous output slab instead of
// interleaving two of each -> better DRAM page locality, concurrent working
// set 262 MB (~TLB reach) instead of 524 MB.
constexpr int N_ = 8;
constexpr int C_ = 16;
constexpr int H_ = 32;
constexpr int W_ = 32;
constexpr int T_ = 500;
constexpr int CHW = C_ * H_ * W_;     // 16384 (power of two)
constexpr int TV  = T_ / 4;           // 125 float4 per row
constexpr int NPER = 4;               // batch rows per thread
constexpr int ROWSTRIDE = CHW * TV;   // 2,048,000 float4 stride between n's (32-bit safe)
constexpr int HALF_GRID = CHW / 2;    // 8192 blocks per n-half

__global__ void __launch_bounds__(256, 6) delay_kernel(
    const float* __restrict__ x,
    const float* __restrict__ delay,
    const uint32_t* __restrict__ ts_bits,
    float* __restrict__ out)
{
    // n-half = HIGH bit of blockIdx; chw pair = low bits. 128 threads per chw.
    int tv  = threadIdx.x & 127;
    int bp  = blockIdx.x & (HALF_GRID - 1);          // chw pair index
    int n0  = (blockIdx.x >= HALF_GRID) ? NPER : 0;  // n-half (wave-contiguous)
    int chw = (bp << 1) | (threadIdx.x >> 7);
    if (tv >= TV) return;

    // Decode Ts robustly (scalar may arrive as int32 or float32 bits).
    uint32_t tb = __ldg(ts_bits);
    float tf = __uint_as_float(tb);
    float Ts = (tf >= 1e-6f && tf <= 1e6f) ? tf : (float)(int)tb;

    // Per-chw shift parameters — shared by all n.
    float s    = __ldg(delay + chw) / Ts;
    float sif  = floorf(s);
    float frac = s - sif;
    int   si   = (int)sif;

    int start = -1 - si;         // first tap offset
    int q0 = start >> 2;         // floor-div-4
    int r  = start & 3;          // warp-uniform extract case

    int vi = tv + q0;
    bool va = (vi     >= 0) && (vi     < TV);
    bool vb = (vi + 1 >= 0) && (vi + 1 < TV);

    // Pure 32-bit indexing: total float4 count = 16.384M << 2^31.
    const float4* __restrict__ x4 = reinterpret_cast<const float4*>(x);
    int abase = (n0 * CHW + chw) * TV + vi;

    // Front-batched independent loads: 8 x LDG.128 in flight (MLP_p1 = 8).
    float4 z = make_float4(0.f, 0.f, 0.f, 0.f);
    float4 A[NPER], B[NPER];
#pragma unroll
    for (int j = 0; j < NPER; ++j) {
        A[j] = va ? __ldg(x4 + (abase + j * ROWSTRIDE))     : z;
        B[j] = vb ? __ldg(x4 + (abase + j * ROWSTRIDE + 1)) : z;
    }

    float w1 = frac;
    float w0 = 1.0f - frac;
    float4* __restrict__ o4 = reinterpret_cast<float4*>(out);
    int obase = (n0 * CHW + chw) * TV + tv;

#pragma unroll
    for (int j = 0; j < NPER; ++j) {
        float l0, l1, l2, l3, l4;
        switch (r) {
            case 0: l0 = A[j].x; l1 = A[j].y; l2 = A[j].z; l3 = A[j].w; l4 = B[j].x; break;
            case 1: l0 = A[j].y; l1 = A[j].z; l2 = A[j].w; l3 = B[j].x; l4 = B[j].y; break;
            case 2: l0 = A[j].z; l1 = A[j].w; l2 = B[j].x; l3 = B[j].y; l4 = B[j].z; break;
            default:l0 = A[j].w; l1 = B[j].x; l2 = B[j].y; l3 = B[j].z; l4 = B[j].w; break;
        }
        float4 o;
        o.x = w0 * l1 + w1 * l0;
        o.y = w0 * l2 + w1 * l1;
        o.z = w0 * l3 + w1 * l2;
        o.w = w0 * l4 + w1 * l3;
        o4[obase + j * ROWSTRIDE] = o;
    }
}

extern "C" void kernel_launch(void* const* d_in, const int* in_sizes, int n_in,
                              void* d_out, int out_size)
{
    const float*    x     = (const float*)d_in[0];
    const float*    delay = (const float*)d_in[1];
    const uint32_t* ts    = (const uint32_t*)d_in[2];
    float*          out   = (float*)d_out;

    // CHW blocks: low bits pick the chw pair, high bit picks the n-half.
    delay_kernel<<<CHW, 256>>>(x, delay, ts, out);
}